// round 2
// baseline (speedup 1.0000x reference)
#include <cuda_runtime.h>
#include <math.h>

#define BDIM  2
#define TSEQ  2048
#define CDIM  2048
#define NHEAD 16
#define HD    128

typedef unsigned long long ull;

// Scratch (static device globals — no runtime allocation)
__device__ float g_qkv[(size_t)BDIM * TSEQ * 3 * CDIM];   // [B,T,3C]
__device__ float g_att[(size_t)BDIM * TSEQ * CDIM];       // [B,T,C]

// ---------------- packed f32x2 helpers ----------------
__device__ __forceinline__ ull pack2(float a, float b) {
    ull r; asm("mov.b64 %0, {%1, %2};" : "=l"(r) : "f"(a), "f"(b)); return r;
}
__device__ __forceinline__ ull bcast2(float a) { return pack2(a, a); }
__device__ __forceinline__ ull fma2(ull a, ull b, ull c) {
    ull d; asm("fma.rn.f32x2 %0, %1, %2, %3;" : "=l"(d) : "l"(a), "l"(b), "l"(c)); return d;
}
__device__ __forceinline__ ull mul2(ull a, ull b) {
    ull d; asm("mul.rn.f32x2 %0, %1, %2;" : "=l"(d) : "l"(a), "l"(b)); return d;
}
__device__ __forceinline__ float2 unpack2(ull v) {
    float2 f; asm("mov.b64 {%0, %1}, %2;" : "=f"(f.x), "=f"(f.y) : "l"(v)); return f;
}

// ---------------------------------------------------------------------------
// SGEMM + bias on packed f32x2: C[M,N] = A[M,K] @ B[K,N] + bias[N]
// Block tile 128(M) x 256(N), BK=16, 256 threads.
// Per thread: 8 M-rows (ty*8..) x 16 N-cols (4 chunks of float4 at tx*4+c*64).
// Accumulators: 8 x 8 f32x2. Register-staged global prefetch.
// ---------------------------------------------------------------------------
#define BM 128
#define BN 256
#define BK 16

__global__ void __launch_bounds__(256) sgemm_bias_kernel(
    const float* __restrict__ A, const float* __restrict__ B,
    const float* __restrict__ bias, float* __restrict__ C,
    int M, int N, int K)
{
    __shared__ float As[BK][BM];   // transposed: As[k][m]
    __shared__ float Bs[BK][BN];   // natural:    Bs[k][n]

    const int tid = threadIdx.x;
    const int tx = tid & 15, ty = tid >> 4;
    const int m0 = blockIdx.y * BM;
    const int n0 = blockIdx.x * BN;

    ull acc[8][8];
    #pragma unroll
    for (int i = 0; i < 8; i++)
        #pragma unroll
        for (int j = 0; j < 8; j++) acc[i][j] = 0ull;

    // load-index precompute
    const int a_r  = tid >> 2;            // 0..63  (with +64 for second)
    const int a_k4 = (tid & 3) * 4;       // 0,4,8,12
    const int b_r  = tid >> 6;            // 0..3   (+4,+8,+12)
    const int b_c4 = (tid & 63) * 4;      // 0..252

    float4 stA[2], stB[4];

    // prologue: load tile 0
    #pragma unroll
    for (int l = 0; l < 2; l++)
        stA[l] = *(const float4*)(A + (size_t)(m0 + a_r + l * 64) * K + a_k4);
    #pragma unroll
    for (int l = 0; l < 4; l++)
        stB[l] = *(const float4*)(B + (size_t)(b_r + l * 4) * N + n0 + b_c4);

    const int iters = K / BK;
    for (int it = 0; it < iters; it++) {
        // store staged tile to smem
        #pragma unroll
        for (int l = 0; l < 2; l++) {
            int r = a_r + l * 64;
            As[a_k4 + 0][r] = stA[l].x;
            As[a_k4 + 1][r] = stA[l].y;
            As[a_k4 + 2][r] = stA[l].z;
            As[a_k4 + 3][r] = stA[l].w;
        }
        #pragma unroll
        for (int l = 0; l < 4; l++)
            *(float4*)&Bs[b_r + l * 4][b_c4] = stB[l];
        __syncthreads();

        // prefetch next tile into regs (overlaps with compute below)
        if (it + 1 < iters) {
            int k0 = (it + 1) * BK;
            #pragma unroll
            for (int l = 0; l < 2; l++)
                stA[l] = *(const float4*)(A + (size_t)(m0 + a_r + l * 64) * K + k0 + a_k4);
            #pragma unroll
            for (int l = 0; l < 4; l++)
                stB[l] = *(const float4*)(B + (size_t)(k0 + b_r + l * 4) * N + n0 + b_c4);
        }

        #pragma unroll
        for (int kk = 0; kk < BK; kk++) {
            float4 a0 = *(float4*)&As[kk][ty * 8];
            float4 a1 = *(float4*)&As[kk][ty * 8 + 4];
            ull a2[8];
            a2[0] = bcast2(a0.x); a2[1] = bcast2(a0.y);
            a2[2] = bcast2(a0.z); a2[3] = bcast2(a0.w);
            a2[4] = bcast2(a1.x); a2[5] = bcast2(a1.y);
            a2[6] = bcast2(a1.z); a2[7] = bcast2(a1.w);

            ull b2[8];
            #pragma unroll
            for (int c = 0; c < 4; c++) {
                float4 b = *(float4*)&Bs[kk][tx * 4 + c * 64];
                b2[2 * c]     = pack2(b.x, b.y);
                b2[2 * c + 1] = pack2(b.z, b.w);
            }
            #pragma unroll
            for (int i = 0; i < 8; i++)
                #pragma unroll
                for (int j = 0; j < 8; j++)
                    acc[i][j] = fma2(a2[i], b2[j], acc[i][j]);
        }
        __syncthreads();
    }

    // Epilogue: bias + store (4 float4 chunks per row)
    float4 bl[4];
    #pragma unroll
    for (int c = 0; c < 4; c++)
        bl[c] = *(const float4*)(bias + n0 + tx * 4 + c * 64);

    #pragma unroll
    for (int i = 0; i < 8; i++) {
        float* cp = C + (size_t)(m0 + ty * 8 + i) * N + n0;
        #pragma unroll
        for (int c = 0; c < 4; c++) {
            float2 lo = unpack2(acc[i][2 * c]);
            float2 hi = unpack2(acc[i][2 * c + 1]);
            float4 o;
            o.x = lo.x + bl[c].x; o.y = lo.y + bl[c].y;
            o.z = hi.x + bl[c].z; o.w = hi.y + bl[c].w;
            *(float4*)(cp + tx * 4 + c * 64) = o;
        }
    }
}

// ---------------------------------------------------------------------------
// FP32 flash attention (causal), f32x2 inner products.
// 64 queries x 64 keys per tile, hd=128. grid=(T/64, NHEAD, B), block=256.
// ---------------------------------------------------------------------------
#define FBM 64
#define FBN 64
#define BMP 68   // padded row stride for transposed tiles

#define FLASH_SMEM ((HD*BMP + HD*BMP + FBN*HD + FBM*65) * 4)

__global__ void __launch_bounds__(256) flash_kernel(
    const float* __restrict__ qkv, float* __restrict__ out)
{
    extern __shared__ float sm[];
    float* Qt = sm;                 // [HD][BMP]
    float* Kt = Qt + HD * BMP;      // [HD][BMP]
    float* Vs = Kt + HD * BMP;      // [FBN][HD]
    float* Ps = Vs + FBN * HD;      // [FBM][65]

    const int qi  = blockIdx.x;
    const int h   = blockIdx.y;
    const int b   = blockIdx.z;
    const int tid = threadIdx.x;
    const int tx  = tid & 15, ty = tid >> 4;
    const int q0  = qi * FBM;
    const float scale_q = 0.08838834764831844f;  // 1/sqrt(128)

    const float* qb = qkv + (size_t)b * TSEQ * 3 * CDIM + h * HD;
    const float* kb = qb + CDIM;
    const float* vb = qb + 2 * CDIM;

    // Load Q tile transposed, pre-scaled
    #pragma unroll
    for (int l = 0; l < 8; l++) {
        int lin = tid + l * 256;
        int r   = lin >> 5;
        int d4  = (lin & 31) * 4;
        float4 v = *(const float4*)(qb + (size_t)(q0 + r) * 3 * CDIM + d4);
        Qt[(d4 + 0) * BMP + r] = v.x * scale_q;
        Qt[(d4 + 1) * BMP + r] = v.y * scale_q;
        Qt[(d4 + 2) * BMP + r] = v.z * scale_q;
        Qt[(d4 + 3) * BMP + r] = v.w * scale_q;
    }

    float m_i[4], l_i[4];
    ull O2[4][4];
    #pragma unroll
    for (int i = 0; i < 4; i++) {
        m_i[i] = -INFINITY; l_i[i] = 0.f;
        #pragma unroll
        for (int j = 0; j < 4; j++) O2[i][j] = 0ull;
    }

    for (int j = 0; j <= qi; j++) {
        __syncthreads();
        // Load K tile transposed + V tile natural
        #pragma unroll
        for (int l = 0; l < 8; l++) {
            int lin = tid + l * 256;
            int r   = lin >> 5;
            int d4  = (lin & 31) * 4;
            size_t goff = (size_t)(j * FBN + r) * 3 * CDIM + d4;
            float4 kv = *(const float4*)(kb + goff);
            Kt[(d4 + 0) * BMP + r] = kv.x;
            Kt[(d4 + 1) * BMP + r] = kv.y;
            Kt[(d4 + 2) * BMP + r] = kv.z;
            Kt[(d4 + 3) * BMP + r] = kv.w;
            *(float4*)&Vs[r * HD + d4] = *(const float4*)(vb + goff);
        }
        __syncthreads();

        // S = Q K^T (4x4 per thread), packed along key axis
        ull s2[4][2];
        #pragma unroll
        for (int i = 0; i < 4; i++) { s2[i][0] = 0ull; s2[i][1] = 0ull; }

        #pragma unroll 8
        for (int d = 0; d < HD; d++) {
            float4 qr = *(float4*)&Qt[d * BMP + ty * 4];
            float4 kr = *(float4*)&Kt[d * BMP + tx * 4];
            ull kp0 = pack2(kr.x, kr.y);
            ull kp1 = pack2(kr.z, kr.w);
            ull qa;
            qa = bcast2(qr.x); s2[0][0] = fma2(qa, kp0, s2[0][0]); s2[0][1] = fma2(qa, kp1, s2[0][1]);
            qa = bcast2(qr.y); s2[1][0] = fma2(qa, kp0, s2[1][0]); s2[1][1] = fma2(qa, kp1, s2[1][1]);
            qa = bcast2(qr.z); s2[2][0] = fma2(qa, kp0, s2[2][0]); s2[2][1] = fma2(qa, kp1, s2[2][1]);
            qa = bcast2(qr.w); s2[3][0] = fma2(qa, kp0, s2[3][0]); s2[3][1] = fma2(qa, kp1, s2[3][1]);
        }

        float acc[4][4];
        #pragma unroll
        for (int i = 0; i < 4; i++) {
            float2 lo = unpack2(s2[i][0]);
            float2 hi = unpack2(s2[i][1]);
            acc[i][0] = lo.x; acc[i][1] = lo.y; acc[i][2] = hi.x; acc[i][3] = hi.y;
        }

        // Causal mask on diagonal tile
        if (j == qi) {
            #pragma unroll
            for (int i = 0; i < 4; i++)
                #pragma unroll
                for (int jj = 0; jj < 4; jj++)
                    if (tx * 4 + jj > ty * 4 + i) acc[i][jj] = -INFINITY;
        }

        // Online softmax (row reductions via shfl across the 16 tx lanes)
        #pragma unroll
        for (int i = 0; i < 4; i++) {
            float rm = fmaxf(fmaxf(acc[i][0], acc[i][1]), fmaxf(acc[i][2], acc[i][3]));
            rm = fmaxf(rm, __shfl_xor_sync(0xffffffffu, rm, 1));
            rm = fmaxf(rm, __shfl_xor_sync(0xffffffffu, rm, 2));
            rm = fmaxf(rm, __shfl_xor_sync(0xffffffffu, rm, 4));
            rm = fmaxf(rm, __shfl_xor_sync(0xffffffffu, rm, 8));
            float mnew = fmaxf(m_i[i], rm);
            float sc   = __expf(m_i[i] - mnew);
            float s = 0.f;
            #pragma unroll
            for (int jj = 0; jj < 4; jj++) {
                float p = __expf(acc[i][jj] - mnew);
                Ps[(ty * 4 + i) * 65 + tx * 4 + jj] = p;
                s += p;
            }
            s += __shfl_xor_sync(0xffffffffu, s, 1);
            s += __shfl_xor_sync(0xffffffffu, s, 2);
            s += __shfl_xor_sync(0xffffffffu, s, 4);
            s += __shfl_xor_sync(0xffffffffu, s, 8);
            l_i[i] = l_i[i] * sc + s;
            m_i[i] = mnew;
            ull sc2 = bcast2(sc);
            #pragma unroll
            for (int jj = 0; jj < 4; jj++) O2[i][jj] = mul2(O2[i][jj], sc2);
        }
        __syncthreads();

        // O += P @ V (4 rows x 8 cols per thread, packed)
        #pragma unroll 4
        for (int kk = 0; kk < FBN; kk++) {
            float4 v0 = *(float4*)&Vs[kk * HD + tx * 8];
            float4 v1 = *(float4*)&Vs[kk * HD + tx * 8 + 4];
            ull vv[4];
            vv[0] = pack2(v0.x, v0.y); vv[1] = pack2(v0.z, v0.w);
            vv[2] = pack2(v1.x, v1.y); vv[3] = pack2(v1.z, v1.w);
            #pragma unroll
            for (int i = 0; i < 4; i++) {
                ull pp = bcast2(Ps[(ty * 4 + i) * 65 + kk]);
                #pragma unroll
                for (int jj = 0; jj < 4; jj++)
                    O2[i][jj] = fma2(pp, vv[jj], O2[i][jj]);
            }
        }
    }

    // Epilogue: normalize, write [B,T,C]
    #pragma unroll
    for (int i = 0; i < 4; i++) {
        float inv = 1.f / l_i[i];
        float o[8];
        #pragma unroll
        for (int jj = 0; jj < 4; jj++) {
            float2 p = unpack2(O2[i][jj]);
            o[2 * jj]     = p.x * inv;
            o[2 * jj + 1] = p.y * inv;
        }
        float* op = out + ((size_t)b * TSEQ + q0 + ty * 4 + i) * CDIM + h * HD + tx * 8;
        *(float4*)op       = *(float4*)&o[0];
        *(float4*)(op + 4) = *(float4*)&o[4];
    }
}

// ---------------------------------------------------------------------------
extern "C" void kernel_launch(void* const* d_in, const int* in_sizes, int n_in,
                              void* d_out, int out_size)
{
    const float* x      = (const float*)d_in[0];
    const float* w_attn = (const float*)d_in[1];
    const float* b_attn = (const float*)d_in[2];
    const float* w_proj = (const float*)d_in[3];
    const float* b_proj = (const float*)d_in[4];
    float* out = (float*)d_out;

    float *qkv, *att;
    cudaGetSymbolAddress((void**)&qkv, g_qkv);
    cudaGetSymbolAddress((void**)&att, g_att);

    cudaFuncSetAttribute(flash_kernel,
                         cudaFuncAttributeMaxDynamicSharedMemorySize, FLASH_SMEM);

    const int M = BDIM * TSEQ;  // 4096

    // 1) QKV = x @ w_attn + b_attn           [4096, 6144]
    sgemm_bias_kernel<<<dim3(3 * CDIM / BN, M / BM), 256>>>(
        x, w_attn, b_attn, qkv, M, 3 * CDIM, CDIM);

    // 2) Flash attention -> g_att            [4096, 2048]
    flash_kernel<<<dim3(TSEQ / FBM, NHEAD, BDIM), 256, FLASH_SMEM>>>(qkv, att);

    // 3) out = att @ w_proj + b_proj         [4096, 2048]
    sgemm_bias_kernel<<<dim3(CDIM / BN, M / BM), 256>>>(
        att, w_proj, b_proj, out, M, CDIM, CDIM);
}

// round 3
// speedup vs baseline: 1.7016x; 1.7016x over previous
#include <cuda_runtime.h>
#include <cuda_bf16.h>
#include <math.h>

#define BDIM  2
#define TSEQ  2048
#define CDIM  2048
#define NHEAD 16
#define HD    128

// Scratch (static device globals — no runtime allocation)
__device__ float g_qkv[(size_t)BDIM * TSEQ * 3 * CDIM];   // [B,T,3C]
__device__ float g_att[(size_t)BDIM * TSEQ * CDIM];       // [B,T,C]

// ---------------- helpers ----------------
__device__ __forceinline__ unsigned smem_u32(const void* p) {
    unsigned a;
    asm("{ .reg .u64 t; cvta.to.shared.u64 t, %1; cvt.u32.u64 %0, t; }"
        : "=r"(a) : "l"(p));
    return a;
}

// Split two fp32 into packed bf16 hi-pair and lo-pair (residual).
__device__ __forceinline__ void split2(float x, float y, unsigned& hi, unsigned& lo) {
    unsigned h;
    asm("cvt.rn.bf16x2.f32 %0, %1, %2;" : "=r"(h) : "f"(y), "f"(x)); // low=x, high=y
    float hx = __uint_as_float(h << 16);
    float hy = __uint_as_float(h & 0xffff0000u);
    float rx = x - hx;
    float ry = y - hy;
    unsigned l;
    asm("cvt.rn.bf16x2.f32 %0, %1, %2;" : "=r"(l) : "f"(ry), "f"(rx));
    hi = h; lo = l;
}

__device__ __forceinline__ void mma16816(float* d, const unsigned* a, const unsigned* b) {
    asm("mma.sync.aligned.m16n8k16.row.col.f32.bf16.bf16.f32 "
        "{%0,%1,%2,%3}, {%4,%5,%6,%7}, {%8,%9}, {%0,%1,%2,%3};"
        : "+f"(d[0]), "+f"(d[1]), "+f"(d[2]), "+f"(d[3])
        : "r"(a[0]), "r"(a[1]), "r"(a[2]), "r"(a[3]), "r"(b[0]), "r"(b[1]));
}

__device__ __forceinline__ void ldsm_x4(unsigned* r, unsigned addr) {
    asm volatile("ldmatrix.sync.aligned.m8n8.x4.shared.b16 {%0,%1,%2,%3}, [%4];"
                 : "=r"(r[0]), "=r"(r[1]), "=r"(r[2]), "=r"(r[3]) : "r"(addr));
}
__device__ __forceinline__ void ldsm_x2t(unsigned* r, unsigned addr) {
    asm volatile("ldmatrix.sync.aligned.m8n8.x2.trans.shared.b16 {%0,%1}, [%2];"
                 : "=r"(r[0]), "=r"(r[1]) : "r"(addr));
}

// ---------------------------------------------------------------------------
// GEMM + bias via bf16 tensor cores, 3-term split (full fp32 accuracy):
//   C = Ah.Bh + Ah.Bl + Al.Bh  (error ~2^-18)
// Block 128x128, BK=32, 256 threads (8 warps, warp tile 64x32).
// smem: A hi/lo [128][40 bf16], B hi/lo [32][136 bf16] (16B-aligned rows,
// conflict-free for ldmatrix).
// ---------------------------------------------------------------------------
#define GBM 128
#define GBN 128
#define GBK 32
#define ASTRIDE 40    // bf16 units (80B, 16B aligned, conflict-free)
#define BSTRIDE 136   // bf16 units (272B)

__global__ void __launch_bounds__(256, 1) gemm_bf16x3_kernel(
    const float* __restrict__ A, const float* __restrict__ B,
    const float* __restrict__ bias, float* __restrict__ C,
    int M, int N, int K)
{
    __shared__ unsigned As_hi[GBM * (ASTRIDE / 2)];   // uint = 2 bf16
    __shared__ unsigned As_lo[GBM * (ASTRIDE / 2)];
    __shared__ unsigned Bs_hi[GBK * (BSTRIDE / 2)];
    __shared__ unsigned Bs_lo[GBK * (BSTRIDE / 2)];

    const int tid  = threadIdx.x;
    const int lane = tid & 31;
    const int warp = tid >> 5;
    const int wm   = warp >> 2;      // 0..1
    const int wn   = warp & 3;       // 0..3
    const int m0   = blockIdx.y * GBM;
    const int n0   = blockIdx.x * GBN;

    float d[4][4][4];
    #pragma unroll
    for (int i = 0; i < 4; i++)
        #pragma unroll
        for (int j = 0; j < 4; j++)
            #pragma unroll
            for (int c = 0; c < 4; c++) d[i][j][c] = 0.f;

    // staging indices
    const int a_c4 = tid & 7;        // float4 col in A tile (BK/4=8)
    const int a_r  = tid >> 3;       // 0..31, rows +32*l
    const int b_c4 = tid & 31;       // float4 col in B tile (BN/4=32)
    const int b_r  = tid >> 5;       // 0..7, rows +8*l

    float4 stA[4], stB[4];
    #pragma unroll
    for (int l = 0; l < 4; l++)
        stA[l] = *(const float4*)(A + (size_t)(m0 + a_r + 32 * l) * K + a_c4 * 4);
    #pragma unroll
    for (int l = 0; l < 4; l++)
        stB[l] = *(const float4*)(B + (size_t)(b_r + 8 * l) * N + n0 + b_c4 * 4);

    // ldmatrix per-lane base offsets (bytes)
    const int aRow = lane & 15;
    const int aCol = (lane >> 4) * 8;
    const unsigned aOff = (unsigned)(((wm * 64 + aRow) * ASTRIDE + aCol) * 2);
    const int bRow = lane & 15;
    const unsigned bOff = (unsigned)((bRow * BSTRIDE + wn * 32) * 2);

    const unsigned aHiB = smem_u32(As_hi) + aOff;
    const unsigned aLoB = smem_u32(As_lo) + aOff;
    const unsigned bHiB = smem_u32(Bs_hi) + bOff;
    const unsigned bLoB = smem_u32(Bs_lo) + bOff;

    const int iters = K / GBK;
    for (int it = 0; it < iters; it++) {
        // convert + store staged tile to smem (hi/lo split)
        #pragma unroll
        for (int l = 0; l < 4; l++) {
            unsigned h0, l0, h1, l1;
            split2(stA[l].x, stA[l].y, h0, l0);
            split2(stA[l].z, stA[l].w, h1, l1);
            int ui = (a_r + 32 * l) * (ASTRIDE / 2) + a_c4 * 2;
            As_hi[ui] = h0; As_hi[ui + 1] = h1;
            As_lo[ui] = l0; As_lo[ui + 1] = l1;
        }
        #pragma unroll
        for (int l = 0; l < 4; l++) {
            unsigned h0, l0, h1, l1;
            split2(stB[l].x, stB[l].y, h0, l0);
            split2(stB[l].z, stB[l].w, h1, l1);
            int ui = (b_r + 8 * l) * (BSTRIDE / 2) + b_c4 * 2;
            Bs_hi[ui] = h0; Bs_hi[ui + 1] = h1;
            Bs_lo[ui] = l0; Bs_lo[ui + 1] = l1;
        }
        __syncthreads();

        // prefetch next tile
        if (it + 1 < iters) {
            int k0 = (it + 1) * GBK;
            #pragma unroll
            for (int l = 0; l < 4; l++)
                stA[l] = *(const float4*)(A + (size_t)(m0 + a_r + 32 * l) * K + k0 + a_c4 * 4);
            #pragma unroll
            for (int l = 0; l < 4; l++)
                stB[l] = *(const float4*)(B + (size_t)(k0 + b_r + 8 * l) * N + n0 + b_c4 * 4);
        }

        #pragma unroll
        for (int kc = 0; kc < GBK; kc += 16) {
            unsigned ah[4][4], al[4][4], bh[4][2], bl[4][2];
            #pragma unroll
            for (int tm = 0; tm < 4; tm++) {
                unsigned off = tm * (16 * ASTRIDE * 2) + kc * 2;
                ldsm_x4(ah[tm], aHiB + off);
                ldsm_x4(al[tm], aLoB + off);
            }
            #pragma unroll
            for (int tn = 0; tn < 4; tn++) {
                unsigned off = kc * (BSTRIDE * 2) + tn * 16;
                ldsm_x2t(bh[tn], bHiB + off);
                ldsm_x2t(bl[tn], bLoB + off);
            }
            #pragma unroll
            for (int tm = 0; tm < 4; tm++)
                #pragma unroll
                for (int tn = 0; tn < 4; tn++) {
                    mma16816(d[tm][tn], ah[tm], bh[tn]);
                    mma16816(d[tm][tn], ah[tm], bl[tn]);
                    mma16816(d[tm][tn], al[tm], bh[tn]);
                }
        }
        __syncthreads();
    }

    // epilogue: bias + store
    const int g = lane >> 2, t4 = lane & 3;
    #pragma unroll
    for (int tn = 0; tn < 4; tn++) {
        int col = n0 + wn * 32 + tn * 8 + t4 * 2;
        float bx = bias[col], by = bias[col + 1];
        #pragma unroll
        for (int tm = 0; tm < 4; tm++) {
            int row0 = m0 + wm * 64 + tm * 16 + g;
            float2 s0 = make_float2(d[tm][tn][0] + bx, d[tm][tn][1] + by);
            float2 s1 = make_float2(d[tm][tn][2] + bx, d[tm][tn][3] + by);
            *(float2*)(C + (size_t)row0 * N + col) = s0;
            *(float2*)(C + (size_t)(row0 + 8) * N + col) = s1;
        }
    }
}

// ---------------------------------------------------------------------------
// FP32 flash attention (causal). 64 queries x 64 keys per tile, hd=128.
// (round-1 version, known good)
// ---------------------------------------------------------------------------
#define FBM 64
#define FBN 64
#define BMP 68

#define FLASH_SMEM ((HD*BMP + HD*BMP + FBN*HD + FBM*65) * 4)

__global__ void __launch_bounds__(256) flash_kernel(
    const float* __restrict__ qkv, float* __restrict__ out)
{
    extern __shared__ float sm[];
    float* Qt = sm;                 // [HD][BMP]
    float* Kt = Qt + HD * BMP;      // [HD][BMP]
    float* Vs = Kt + HD * BMP;      // [FBN][HD]
    float* Ps = Vs + FBN * HD;      // [FBM][65]

    const int qi  = blockIdx.x;
    const int h   = blockIdx.y;
    const int b   = blockIdx.z;
    const int tid = threadIdx.x;
    const int tx  = tid & 15, ty = tid >> 4;
    const int q0  = qi * FBM;
    const float scale_q = 0.08838834764831844f;  // 1/sqrt(128)

    const float* qb = qkv + (size_t)b * TSEQ * 3 * CDIM + h * HD;
    const float* kb = qb + CDIM;
    const float* vb = qb + 2 * CDIM;

    #pragma unroll
    for (int l = 0; l < 8; l++) {
        int lin = tid + l * 256;
        int r   = lin >> 5;
        int d4  = (lin & 31) * 4;
        float4 v = *(const float4*)(qb + (size_t)(q0 + r) * 3 * CDIM + d4);
        Qt[(d4 + 0) * BMP + r] = v.x * scale_q;
        Qt[(d4 + 1) * BMP + r] = v.y * scale_q;
        Qt[(d4 + 2) * BMP + r] = v.z * scale_q;
        Qt[(d4 + 3) * BMP + r] = v.w * scale_q;
    }

    float m_i[4], l_i[4], O[4][8];
    #pragma unroll
    for (int i = 0; i < 4; i++) {
        m_i[i] = -INFINITY; l_i[i] = 0.f;
        #pragma unroll
        for (int j = 0; j < 8; j++) O[i][j] = 0.f;
    }

    for (int j = 0; j <= qi; j++) {
        __syncthreads();
        #pragma unroll
        for (int l = 0; l < 8; l++) {
            int lin = tid + l * 256;
            int r   = lin >> 5;
            int d4  = (lin & 31) * 4;
            size_t goff = (size_t)(j * FBN + r) * 3 * CDIM + d4;
            float4 kv = *(const float4*)(kb + goff);
            Kt[(d4 + 0) * BMP + r] = kv.x;
            Kt[(d4 + 1) * BMP + r] = kv.y;
            Kt[(d4 + 2) * BMP + r] = kv.z;
            Kt[(d4 + 3) * BMP + r] = kv.w;
            *(float4*)&Vs[r * HD + d4] = *(const float4*)(vb + goff);
        }
        __syncthreads();

        float acc[4][4];
        #pragma unroll
        for (int i = 0; i < 4; i++)
            #pragma unroll
            for (int jj = 0; jj < 4; jj++) acc[i][jj] = 0.f;

        #pragma unroll 8
        for (int dd = 0; dd < HD; dd++) {
            float qr[4], kr[4];
            *(float4*)qr = *(float4*)&Qt[dd * BMP + ty * 4];
            *(float4*)kr = *(float4*)&Kt[dd * BMP + tx * 4];
            #pragma unroll
            for (int i = 0; i < 4; i++)
                #pragma unroll
                for (int jj = 0; jj < 4; jj++)
                    acc[i][jj] = fmaf(qr[i], kr[jj], acc[i][jj]);
        }

        if (j == qi) {
            #pragma unroll
            for (int i = 0; i < 4; i++)
                #pragma unroll
                for (int jj = 0; jj < 4; jj++)
                    if (tx * 4 + jj > ty * 4 + i) acc[i][jj] = -INFINITY;
        }

        #pragma unroll
        for (int i = 0; i < 4; i++) {
            float rm = fmaxf(fmaxf(acc[i][0], acc[i][1]), fmaxf(acc[i][2], acc[i][3]));
            rm = fmaxf(rm, __shfl_xor_sync(0xffffffffu, rm, 1));
            rm = fmaxf(rm, __shfl_xor_sync(0xffffffffu, rm, 2));
            rm = fmaxf(rm, __shfl_xor_sync(0xffffffffu, rm, 4));
            rm = fmaxf(rm, __shfl_xor_sync(0xffffffffu, rm, 8));
            float mnew = fmaxf(m_i[i], rm);
            float sc   = __expf(m_i[i] - mnew);
            float s = 0.f;
            #pragma unroll
            for (int jj = 0; jj < 4; jj++) {
                float p = __expf(acc[i][jj] - mnew);
                Ps[(ty * 4 + i) * 65 + tx * 4 + jj] = p;
                s += p;
            }
            s += __shfl_xor_sync(0xffffffffu, s, 1);
            s += __shfl_xor_sync(0xffffffffu, s, 2);
            s += __shfl_xor_sync(0xffffffffu, s, 4);
            s += __shfl_xor_sync(0xffffffffu, s, 8);
            l_i[i] = l_i[i] * sc + s;
            m_i[i] = mnew;
            #pragma unroll
            for (int jj = 0; jj < 8; jj++) O[i][jj] *= sc;
        }
        __syncthreads();

        #pragma unroll 4
        for (int kk = 0; kk < FBN; kk++) {
            float vr[8];
            *(float4*)&vr[0] = *(float4*)&Vs[kk * HD + tx * 8];
            *(float4*)&vr[4] = *(float4*)&Vs[kk * HD + tx * 8 + 4];
            #pragma unroll
            for (int i = 0; i < 4; i++) {
                float p = Ps[(ty * 4 + i) * 65 + kk];
                #pragma unroll
                for (int jj = 0; jj < 8; jj++)
                    O[i][jj] = fmaf(p, vr[jj], O[i][jj]);
            }
        }
    }

    #pragma unroll
    for (int i = 0; i < 4; i++) {
        float inv = 1.f / l_i[i];
        float o[8];
        #pragma unroll
        for (int jj = 0; jj < 8; jj++) o[jj] = O[i][jj] * inv;
        float* op = out + ((size_t)b * TSEQ + q0 + ty * 4 + i) * CDIM + h * HD + tx * 8;
        *(float4*)op       = *(float4*)&o[0];
        *(float4*)(op + 4) = *(float4*)&o[4];
    }
}

// ---------------------------------------------------------------------------
extern "C" void kernel_launch(void* const* d_in, const int* in_sizes, int n_in,
                              void* d_out, int out_size)
{
    const float* x      = (const float*)d_in[0];
    const float* w_attn = (const float*)d_in[1];
    const float* b_attn = (const float*)d_in[2];
    const float* w_proj = (const float*)d_in[3];
    const float* b_proj = (const float*)d_in[4];
    float* out = (float*)d_out;

    float *qkv, *att;
    cudaGetSymbolAddress((void**)&qkv, g_qkv);
    cudaGetSymbolAddress((void**)&att, g_att);

    cudaFuncSetAttribute(flash_kernel,
                         cudaFuncAttributeMaxDynamicSharedMemorySize, FLASH_SMEM);

    const int M = BDIM * TSEQ;  // 4096

    // 1) QKV = x @ w_attn + b_attn           [4096, 6144]
    gemm_bf16x3_kernel<<<dim3(3 * CDIM / GBN, M / GBM), 256>>>(
        x, w_attn, b_attn, qkv, M, 3 * CDIM, CDIM);

    // 2) Flash attention -> g_att            [4096, 2048]
    flash_kernel<<<dim3(TSEQ / FBM, NHEAD, BDIM), 256, FLASH_SMEM>>>(qkv, att);

    // 3) out = att @ w_proj + b_proj         [4096, 2048]
    gemm_bf16x3_kernel<<<dim3(CDIM / GBN, M / GBM), 256>>>(
        att, w_proj, b_proj, out, M, CDIM, CDIM);
}

// round 5
// speedup vs baseline: 2.8473x; 1.6734x over previous
#include <cuda_runtime.h>
#include <cuda_bf16.h>
#include <math.h>

#define BDIM  2
#define TSEQ  2048
#define CDIM  2048
#define NHEAD 16
#define HD    128

// Scratch (static device globals — no runtime allocation)
__device__ float g_qkv[(size_t)BDIM * TSEQ * 3 * CDIM];   // [B,T,3C]
__device__ float g_att[(size_t)BDIM * TSEQ * CDIM];       // [B,T,C]

// ---------------- helpers ----------------
__device__ __forceinline__ unsigned smem_u32(const void* p) {
    unsigned a;
    asm("{ .reg .u64 t; cvta.to.shared.u64 t, %1; cvt.u32.u64 %0, t; }"
        : "=r"(a) : "l"(p));
    return a;
}

// Split two fp32 into packed bf16 hi-pair and lo-pair (residual).
// Pair layout: low 16 bits = first value, high 16 bits = second value.
__device__ __forceinline__ void split2(float x, float y, unsigned& hi, unsigned& lo) {
    unsigned h;
    asm("cvt.rn.bf16x2.f32 %0, %1, %2;" : "=r"(h) : "f"(y), "f"(x));
    float hx = __uint_as_float(h << 16);
    float hy = __uint_as_float(h & 0xffff0000u);
    float rx = x - hx;
    float ry = y - hy;
    unsigned l;
    asm("cvt.rn.bf16x2.f32 %0, %1, %2;" : "=r"(l) : "f"(ry), "f"(rx));
    hi = h; lo = l;
}

__device__ __forceinline__ void mma16816(float* d, const unsigned* a, const unsigned* b) {
    asm("mma.sync.aligned.m16n8k16.row.col.f32.bf16.bf16.f32 "
        "{%0,%1,%2,%3}, {%4,%5,%6,%7}, {%8,%9}, {%0,%1,%2,%3};"
        : "+f"(d[0]), "+f"(d[1]), "+f"(d[2]), "+f"(d[3])
        : "r"(a[0]), "r"(a[1]), "r"(a[2]), "r"(a[3]), "r"(b[0]), "r"(b[1]));
}

__device__ __forceinline__ void ldsm_x4(unsigned* r, unsigned addr) {
    asm volatile("ldmatrix.sync.aligned.m8n8.x4.shared.b16 {%0,%1,%2,%3}, [%4];"
                 : "=r"(r[0]), "=r"(r[1]), "=r"(r[2]), "=r"(r[3]) : "r"(addr));
}
__device__ __forceinline__ void ldsm_x2(unsigned* r, unsigned addr) {
    asm volatile("ldmatrix.sync.aligned.m8n8.x2.shared.b16 {%0,%1}, [%2];"
                 : "=r"(r[0]), "=r"(r[1]) : "r"(addr));
}
__device__ __forceinline__ void ldsm_x2t(unsigned* r, unsigned addr) {
    asm volatile("ldmatrix.sync.aligned.m8n8.x2.trans.shared.b16 {%0,%1}, [%2];"
                 : "=r"(r[0]), "=r"(r[1]) : "r"(addr));
}

// ---------------------------------------------------------------------------
// GEMM + bias via bf16 tensor cores, 3-term split (round-3, known good)
// ---------------------------------------------------------------------------
#define GBM 128
#define GBN 128
#define GBK 32
#define ASTRIDE 40
#define BSTRIDE 136

__global__ void __launch_bounds__(256, 1) gemm_bf16x3_kernel(
    const float* __restrict__ A, const float* __restrict__ B,
    const float* __restrict__ bias, float* __restrict__ C,
    int M, int N, int K)
{
    __shared__ unsigned As_hi[GBM * (ASTRIDE / 2)];
    __shared__ unsigned As_lo[GBM * (ASTRIDE / 2)];
    __shared__ unsigned Bs_hi[GBK * (BSTRIDE / 2)];
    __shared__ unsigned Bs_lo[GBK * (BSTRIDE / 2)];

    const int tid  = threadIdx.x;
    const int lane = tid & 31;
    const int warp = tid >> 5;
    const int wm   = warp >> 2;
    const int wn   = warp & 3;
    const int m0   = blockIdx.y * GBM;
    const int n0   = blockIdx.x * GBN;

    float d[4][4][4];
    #pragma unroll
    for (int i = 0; i < 4; i++)
        #pragma unroll
        for (int j = 0; j < 4; j++)
            #pragma unroll
            for (int c = 0; c < 4; c++) d[i][j][c] = 0.f;

    const int a_c4 = tid & 7;
    const int a_r  = tid >> 3;
    const int b_c4 = tid & 31;
    const int b_r  = tid >> 5;

    float4 stA[4], stB[4];
    #pragma unroll
    for (int l = 0; l < 4; l++)
        stA[l] = *(const float4*)(A + (size_t)(m0 + a_r + 32 * l) * K + a_c4 * 4);
    #pragma unroll
    for (int l = 0; l < 4; l++)
        stB[l] = *(const float4*)(B + (size_t)(b_r + 8 * l) * N + n0 + b_c4 * 4);

    const int aRow = lane & 15;
    const int aCol = (lane >> 4) * 8;
    const unsigned aOff = (unsigned)(((wm * 64 + aRow) * ASTRIDE + aCol) * 2);
    const int bRow = lane & 15;
    const unsigned bOff = (unsigned)((bRow * BSTRIDE + wn * 32) * 2);

    const unsigned aHiB = smem_u32(As_hi) + aOff;
    const unsigned aLoB = smem_u32(As_lo) + aOff;
    const unsigned bHiB = smem_u32(Bs_hi) + bOff;
    const unsigned bLoB = smem_u32(Bs_lo) + bOff;

    const int iters = K / GBK;
    for (int it = 0; it < iters; it++) {
        #pragma unroll
        for (int l = 0; l < 4; l++) {
            unsigned h0, l0, h1, l1;
            split2(stA[l].x, stA[l].y, h0, l0);
            split2(stA[l].z, stA[l].w, h1, l1);
            int ui = (a_r + 32 * l) * (ASTRIDE / 2) + a_c4 * 2;
            As_hi[ui] = h0; As_hi[ui + 1] = h1;
            As_lo[ui] = l0; As_lo[ui + 1] = l1;
        }
        #pragma unroll
        for (int l = 0; l < 4; l++) {
            unsigned h0, l0, h1, l1;
            split2(stB[l].x, stB[l].y, h0, l0);
            split2(stB[l].z, stB[l].w, h1, l1);
            int ui = (b_r + 8 * l) * (BSTRIDE / 2) + b_c4 * 2;
            Bs_hi[ui] = h0; Bs_hi[ui + 1] = h1;
            Bs_lo[ui] = l0; Bs_lo[ui + 1] = l1;
        }
        __syncthreads();

        if (it + 1 < iters) {
            int k0 = (it + 1) * GBK;
            #pragma unroll
            for (int l = 0; l < 4; l++)
                stA[l] = *(const float4*)(A + (size_t)(m0 + a_r + 32 * l) * K + k0 + a_c4 * 4);
            #pragma unroll
            for (int l = 0; l < 4; l++)
                stB[l] = *(const float4*)(B + (size_t)(k0 + b_r + 8 * l) * N + n0 + b_c4 * 4);
        }

        #pragma unroll
        for (int kc = 0; kc < GBK; kc += 16) {
            unsigned ah[4][4], al[4][4], bh[4][2], bl[4][2];
            #pragma unroll
            for (int tm = 0; tm < 4; tm++) {
                unsigned off = tm * (16 * ASTRIDE * 2) + kc * 2;
                ldsm_x4(ah[tm], aHiB + off);
                ldsm_x4(al[tm], aLoB + off);
            }
            #pragma unroll
            for (int tn = 0; tn < 4; tn++) {
                unsigned off = kc * (BSTRIDE * 2) + tn * 16;
                ldsm_x2t(bh[tn], bHiB + off);
                ldsm_x2t(bl[tn], bLoB + off);
            }
            #pragma unroll
            for (int tm = 0; tm < 4; tm++)
                #pragma unroll
                for (int tn = 0; tn < 4; tn++) {
                    mma16816(d[tm][tn], ah[tm], bh[tn]);
                    mma16816(d[tm][tn], ah[tm], bl[tn]);
                    mma16816(d[tm][tn], al[tm], bh[tn]);
                }
        }
        __syncthreads();
    }

    const int g = lane >> 2, t4 = lane & 3;
    #pragma unroll
    for (int tn = 0; tn < 4; tn++) {
        int col = n0 + wn * 32 + tn * 8 + t4 * 2;
        float bx = bias[col], by = bias[col + 1];
        #pragma unroll
        for (int tm = 0; tm < 4; tm++) {
            int row0 = m0 + wm * 64 + tm * 16 + g;
            float2 s0 = make_float2(d[tm][tn][0] + bx, d[tm][tn][1] + by);
            float2 s1 = make_float2(d[tm][tn][2] + bx, d[tm][tn][3] + by);
            *(float2*)(C + (size_t)row0 * N + col) = s0;
            *(float2*)(C + (size_t)(row0 + 8) * N + col) = s1;
        }
    }
}

// ---------------------------------------------------------------------------
// Tensor-core flash attention (causal), bf16 3-term split, fp32 accumulate.
// Block: 128 queries; KV tiles of 64 keys. 8 warps, each 16 query rows.
// smem: Q/K/V each split hi/lo, row stride 136 bf16 (conflict-free ldmatrix).
// ---------------------------------------------------------------------------
#define FQ 128
#define FK 64
#define QSTR 136          // bf16 units per row
#define QSTRU 68          // uint units per row

// uint offsets in dynamic smem
#define OFF_QH 0
#define OFF_QL (128 * QSTRU)               // 8704
#define OFF_KH (OFF_QL + 128 * QSTRU)      // 17408
#define OFF_KL (OFF_KH + 64 * QSTRU)       // 21760
#define OFF_VH (OFF_KL + 64 * QSTRU)       // 26112
#define OFF_VL (OFF_VH + 64 * QSTRU)       // 30464
#define FLASH_SMEM ((OFF_VL + 64 * QSTRU) * 4)   // 139264 bytes

__global__ void __launch_bounds__(256, 1) flash_mma_kernel(
    const float* __restrict__ qkv, float* __restrict__ out)
{
    extern __shared__ unsigned fsm[];
    const unsigned base = smem_u32(fsm);

    const int tid  = threadIdx.x;
    const int lane = tid & 31;
    const int wm   = tid >> 5;          // 0..7 : 16 query rows each
    const int g    = lane >> 2;
    const int t4   = lane & 3;

    const int qi = blockIdx.x;
    const int h  = blockIdx.y;
    const int b  = blockIdx.z;
    const int q0 = qi * FQ;
    const float scale_q = 0.08838834764831844f;  // 1/sqrt(128)

    const float* qb = qkv + (size_t)b * TSEQ * 3 * CDIM + h * HD;
    const float* kb = qb + CDIM;
    const float* vb = qb + 2 * CDIM;

    // ---- load + split Q tile (128 x 128), pre-scaled ----
    #pragma unroll
    for (int l = 0; l < 16; l++) {
        int lin = tid + l * 256;
        int r   = lin >> 5;             // 0..127
        int c   = lin & 31;             // float4 index
        float4 v = *(const float4*)(qb + (size_t)(q0 + r) * 3 * CDIM + c * 4);
        unsigned h0, l0, h1, l1;
        split2(v.x * scale_q, v.y * scale_q, h0, l0);
        split2(v.z * scale_q, v.w * scale_q, h1, l1);
        int ui = r * QSTRU + c * 2;
        fsm[OFF_QH + ui] = h0; fsm[OFF_QH + ui + 1] = h1;
        fsm[OFF_QL + ui] = l0; fsm[OFF_QL + ui + 1] = l1;
    }
    __syncthreads();

    // hoist Qh A-fragments (8 k-steps)
    unsigned qh[8][4];
    const unsigned aoff = (unsigned)(((wm * 16 + (lane & 15)) * QSTR + (lane >> 4) * 8) * 2);
    #pragma unroll
    for (int ks = 0; ks < 8; ks++)
        ldsm_x4(qh[ks], base + OFF_QH * 4 + aoff + ks * 32);

    float m0r = -INFINITY, m1r = -INFINITY, l0r = 0.f, l1r = 0.f;
    float O[16][4];
    #pragma unroll
    for (int dt = 0; dt < 16; dt++)
        #pragma unroll
        for (int c = 0; c < 4; c++) O[dt][c] = 0.f;

    const int jmax = 2 * qi + 2;
    for (int j = 0; j < jmax; j++) {
        __syncthreads();
        // ---- load + split K,V tile (64 x 128) ----
        #pragma unroll
        for (int l = 0; l < 8; l++) {
            int lin = tid + l * 256;
            int r   = lin >> 5;          // 0..63
            int c   = lin & 31;
            size_t goff = (size_t)(j * FK + r) * 3 * CDIM + c * 4;
            int ui = r * QSTRU + c * 2;
            float4 kv = *(const float4*)(kb + goff);
            unsigned h0, lo0, h1, lo1;
            split2(kv.x, kv.y, h0, lo0);
            split2(kv.z, kv.w, h1, lo1);
            fsm[OFF_KH + ui] = h0; fsm[OFF_KH + ui + 1] = h1;
            fsm[OFF_KL + ui] = lo0; fsm[OFF_KL + ui + 1] = lo1;
            float4 vv = *(const float4*)(vb + goff);
            split2(vv.x, vv.y, h0, lo0);
            split2(vv.z, vv.w, h1, lo1);
            fsm[OFF_VH + ui] = h0; fsm[OFF_VH + ui + 1] = h1;
            fsm[OFF_VL + ui] = lo0; fsm[OFF_VL + ui + 1] = lo1;
        }
        __syncthreads();

        // ---- S = Q K^T (warp tile 16 x 64) ----
        float S[8][4];
        #pragma unroll
        for (int nt = 0; nt < 8; nt++)
            #pragma unroll
            for (int c = 0; c < 4; c++) S[nt][c] = 0.f;

        const unsigned kRowOff = (unsigned)((((lane & 7)) * QSTR + ((lane >> 3) & 1) * 8) * 2);
        #pragma unroll
        for (int ks = 0; ks < 8; ks++) {
            unsigned ql_[4];
            ldsm_x4(ql_, base + OFF_QL * 4 + aoff + ks * 32);
            #pragma unroll
            for (int nt = 0; nt < 8; nt++) {
                unsigned koff = kRowOff + (unsigned)((nt * 8 * QSTR + ks * 16) * 2);
                unsigned kh_[2], kl_[2];
                ldsm_x2(kh_, base + OFF_KH * 4 + koff);
                ldsm_x2(kl_, base + OFF_KL * 4 + koff);
                mma16816(S[nt], qh[ks], kh_);
                mma16816(S[nt], qh[ks], kl_);
                mma16816(S[nt], ql_, kh_);
            }
        }

        // ---- causal mask (only near-diagonal tiles) ----
        const int rg0 = q0 + wm * 16 + g;
        const int rg1 = rg0 + 8;
        if (j * FK + FK - 1 > q0 + wm * 16) {
            #pragma unroll
            for (int nt = 0; nt < 8; nt++) {
                int kg = j * FK + nt * 8 + 2 * t4;
                if (kg     > rg0) S[nt][0] = -INFINITY;
                if (kg + 1 > rg0) S[nt][1] = -INFINITY;
                if (kg     > rg1) S[nt][2] = -INFINITY;
                if (kg + 1 > rg1) S[nt][3] = -INFINITY;
            }
        }

        // ---- online softmax ----
        float mx0 = -INFINITY, mx1 = -INFINITY;
        #pragma unroll
        for (int nt = 0; nt < 8; nt++) {
            mx0 = fmaxf(mx0, fmaxf(S[nt][0], S[nt][1]));
            mx1 = fmaxf(mx1, fmaxf(S[nt][2], S[nt][3]));
        }
        mx0 = fmaxf(mx0, __shfl_xor_sync(0xffffffffu, mx0, 1));
        mx0 = fmaxf(mx0, __shfl_xor_sync(0xffffffffu, mx0, 2));
        mx1 = fmaxf(mx1, __shfl_xor_sync(0xffffffffu, mx1, 1));
        mx1 = fmaxf(mx1, __shfl_xor_sync(0xffffffffu, mx1, 2));
        float mn0 = fmaxf(m0r, mx0), mn1 = fmaxf(m1r, mx1);
        float sc0 = __expf(m0r - mn0), sc1 = __expf(m1r - mn1);
        m0r = mn0; m1r = mn1;

        float sum0 = 0.f, sum1 = 0.f;
        unsigned phi[16], plo[16];
        #pragma unroll
        for (int nt = 0; nt < 8; nt++) {
            float p0 = __expf(S[nt][0] - mn0);
            float p1 = __expf(S[nt][1] - mn0);
            float p2 = __expf(S[nt][2] - mn1);
            float p3 = __expf(S[nt][3] - mn1);
            sum0 += p0 + p1; sum1 += p2 + p3;
            split2(p0, p1, phi[2 * nt],     plo[2 * nt]);
            split2(p2, p3, phi[2 * nt + 1], plo[2 * nt + 1]);
        }
        sum0 += __shfl_xor_sync(0xffffffffu, sum0, 1);
        sum0 += __shfl_xor_sync(0xffffffffu, sum0, 2);
        sum1 += __shfl_xor_sync(0xffffffffu, sum1, 1);
        sum1 += __shfl_xor_sync(0xffffffffu, sum1, 2);
        l0r = l0r * sc0 + sum0;
        l1r = l1r * sc1 + sum1;

        #pragma unroll
        for (int dt = 0; dt < 16; dt++) {
            O[dt][0] *= sc0; O[dt][1] *= sc0;
            O[dt][2] *= sc1; O[dt][3] *= sc1;
        }

        // ---- O += P V  (k over 64 keys = 4 k-steps) ----
        const unsigned vRowOff = (unsigned)(((lane & 15) * QSTR) * 2);
        #pragma unroll
        for (int ks = 0; ks < 4; ks++) {
            unsigned pa_h[4] = {phi[4 * ks], phi[4 * ks + 1], phi[4 * ks + 2], phi[4 * ks + 3]};
            unsigned pa_l[4] = {plo[4 * ks], plo[4 * ks + 1], plo[4 * ks + 2], plo[4 * ks + 3]};
            #pragma unroll
            for (int dt = 0; dt < 16; dt++) {
                unsigned voff = vRowOff + (unsigned)((ks * 16 * QSTR + dt * 8) * 2);
                unsigned vh_[2], vl_[2];
                ldsm_x2t(vh_, base + OFF_VH * 4 + voff);
                ldsm_x2t(vl_, base + OFF_VL * 4 + voff);
                mma16816(O[dt], pa_h, vh_);
                mma16816(O[dt], pa_h, vl_);
                mma16816(O[dt], pa_l, vh_);
            }
        }
    }

    // ---- epilogue: normalize + store ----
    float inv0 = 1.f / l0r, inv1 = 1.f / l1r;
    const int rg0 = q0 + wm * 16 + g;
    float* ob = out + ((size_t)b * TSEQ) * CDIM + h * HD;
    #pragma unroll
    for (int dt = 0; dt < 16; dt++) {
        int col = dt * 8 + 2 * t4;
        *(float2*)(ob + (size_t)rg0 * CDIM + col) =
            make_float2(O[dt][0] * inv0, O[dt][1] * inv0);
        *(float2*)(ob + (size_t)(rg0 + 8) * CDIM + col) =
            make_float2(O[dt][2] * inv1, O[dt][3] * inv1);
    }
}

// ---------------------------------------------------------------------------
extern "C" void kernel_launch(void* const* d_in, const int* in_sizes, int n_in,
                              void* d_out, int out_size)
{
    const float* x      = (const float*)d_in[0];
    const float* w_attn = (const float*)d_in[1];
    const float* b_attn = (const float*)d_in[2];
    const float* w_proj = (const float*)d_in[3];
    const float* b_proj = (const float*)d_in[4];
    float* out = (float*)d_out;

    float *qkv, *att;
    cudaGetSymbolAddress((void**)&qkv, g_qkv);
    cudaGetSymbolAddress((void**)&att, g_att);

    cudaFuncSetAttribute(flash_mma_kernel,
                         cudaFuncAttributeMaxDynamicSharedMemorySize, FLASH_SMEM);

    const int M = BDIM * TSEQ;  // 4096

    // 1) QKV = x @ w_attn + b_attn           [4096, 6144]
    gemm_bf16x3_kernel<<<dim3(3 * CDIM / GBN, M / GBM), 256>>>(
        x, w_attn, b_attn, qkv, M, 3 * CDIM, CDIM);

    // 2) Flash attention (tensor cores) -> g_att
    flash_mma_kernel<<<dim3(TSEQ / FQ, NHEAD, BDIM), 256, FLASH_SMEM>>>(qkv, att);

    // 3) out = att @ w_proj + b_proj         [4096, 2048]
    gemm_bf16x3_kernel<<<dim3(CDIM / GBN, M / GBM), 256>>>(
        att, w_proj, b_proj, out, M, CDIM, CDIM);
}